// round 11
// baseline (speedup 1.0000x reference)
#include <cuda_runtime.h>
#include <cstddef>

#define Bc 32
#define Tc 1000
#define Vc 1024
#define Lc 128
#define Sc 257          // 2L+1
#define SP 288          // padded row stride (states 0..287; 257+ are zero)
#define NEGF (-1e30f)
#define KC 16           // DP steps per chunk (barrier period)
#define NCH 63          // chunks: t = 1..1008 (tail frozen by t<hlen)
#define LOGV 6.93147180559945f   // ln(1024): probability pre-scale

// Scratch: g_p[b][t][s] = softmax prob at extended label s, scaled by V=1024
__device__ float g_p[(size_t)Bc * Tc * SP];
__device__ float g_loss[Bc];

// ---------------------------------------------------------------------------
// Kernel 1: 8 (b,t) rows per block. Deep-MLP loads, per-warp row reductions,
// gather at extended labels. Stores p*1024.
// ---------------------------------------------------------------------------
__global__ void __launch_bounds__(256) k_prob(const float* __restrict__ hs,
                                              const int* __restrict__ ys)
{
    __shared__ float se[8 * Vc];      // 32 KB: exp values, 8 rows
    __shared__ float sred[8 * 256];   // 8 KB: per-thread partial sums
    __shared__ float sinvs[8];
    __shared__ int   sy[Lc];

    const int blk = blockIdx.x;
    const int b   = blk / 125;        // 125 blocks of 8 rows per batch
    const int bt0 = blk * 8;
    const int tid = threadIdx.x;

    if (tid < Lc) sy[tid] = ys[b * Lc + tid];

    // Issue all 8 row loads up front (MLP = 8)
    float4 v[8];
#pragma unroll
    for (int r = 0; r < 8; r++)
        v[r] = ((const float4*)(hs + (size_t)(bt0 + r) * Vc))[tid];

#pragma unroll
    for (int r = 0; r < 8; r++) {
        float4 e = make_float4(__expf(v[r].x), __expf(v[r].y),
                               __expf(v[r].z), __expf(v[r].w));
        ((float4*)se)[r * 256 + tid] = e;
        sred[r * 256 + tid] = e.x + e.y + e.z + e.w;
    }
    __syncthreads();

    // Warp w reduces row w
    {
        const int w = tid >> 5, l = tid & 31;
        float acc = 0.f;
#pragma unroll
        for (int j = 0; j < 8; j++) acc += sred[w * 256 + j * 32 + l];
#pragma unroll
        for (int o = 16; o; o >>= 1) acc += __shfl_xor_sync(0xffffffffu, acc, o);
        if (l == 0) sinvs[w] = 1024.0f / acc;
    }
    __syncthreads();

    const int lbl = (tid & 1) ? sy[tid >> 1] : 0;
#pragma unroll
    for (int r = 0; r < 8; r++) {
        float* outr = g_p + (size_t)(bt0 + r) * SP;
        const float si = sinvs[r];
        outr[tid] = se[r * Vc + lbl] * si;
        if (tid < 32)   // s=256 blank; s=257..287 zero padding
            outr[256 + tid] = (tid == 0) ? se[r * Vc] * si : 0.0f;
    }
}

// ---------------------------------------------------------------------------
// Kernel 2: CTC forward DP, linear domain, warp-private halo chunks.
// (Proven R5 structure: 9 warps; lane holds state pair (2i, 2i+1),
// i = w*16 + l - 16; lanes 0..15 = redundant 32-state halo.)
// Only change vs R5: SP=288 / sbuf[2][288] so warp 8's writes are in-bounds.
// ---------------------------------------------------------------------------
__global__ void __launch_bounds__(288) k_ctc_dp(const int* __restrict__ ys,
                                                const int* __restrict__ hlens,
                                                const int* __restrict__ ylens)
{
    __shared__ float sbuf[2][SP];     // alpha (log domain) at chunk boundaries

    const int b   = blockIdx.x;
    const int tid = threadIdx.x;
    const int w   = tid >> 5;
    const int l   = tid & 31;
    const int i   = w * 16 + l - 16;           // pair index: states (2i, 2i+1)
    const bool pv  = (i >= 0 && i <= 128);     // even state 2i valid
    const bool ov  = (i >= 0 && i <= 127);     // odd state 2i+1 valid
    const bool own = (l >= 16) && pv;

    float skf = 0.f;
    if (i >= 1 && i <= 127)
        skf = (ys[b * Lc + i] != ys[b * Lc + i - 1]) ? 1.f : 0.f;

    const int hlen = hlens[b];
    const float* pc = g_p + ((size_t)b * Tc) * SP + 2 * i;   // deref only when pv

    // t = 0 init (true log domain: undo the 1024 scale)
    if (own) {
        float a0 = (i == 0) ? (__logf(pc[0]) - LOGV) : NEGF;
        float a1 = (i == 0) ? (__logf(pc[1]) - LOGV) : NEGF;
        sbuf[0][2 * i] = a0;
        if (ov) sbuf[0][2 * i + 1] = a1;
        else if (i == 128) sbuf[0][257] = NEGF;
    }
    __syncthreads();

    // Prefetch queue: scaled probs for chunk 0 (t = 1..KC)
    float q[2 * KC];
#pragma unroll
    for (int k = 0; k < KC; k++) {
        int t = 1 + k;
        float2 pq = (pv && t <= Tc - 1) ? *(const float2*)(pc + (size_t)t * SP)
                                        : make_float2(0.f, 0.f);
        q[2 * k] = pq.x; q[2 * k + 1] = pq.y;
    }

    int nb = 0;
    for (int c = 0; c < NCH; c++) {
        float ae = pv ? sbuf[nb][2 * i]     : NEGF;
        float ao = ov ? sbuf[nb][2 * i + 1] : NEGF;
        float m = fmaxf(ae, ao);
#pragma unroll
        for (int o = 16; o; o >>= 1) m = fmaxf(m, __shfl_xor_sync(0xffffffffu, m, o));
        m = fmaxf(m, -1e28f);
        float Ae = __expf(ae - m);
        float Ao = __expf(ao - m);
        float lc = 0.f;

        const int t0 = 1 + KC * c;
        int n_sc = hlen - t0;
        n_sc = (n_sc < 0) ? 0 : (n_sc > KC ? KC : n_sc);

#pragma unroll
        for (int k = 0; k < KC; k++) {
            const int t  = t0 + k;
            const float pe = q[2 * k], po = q[2 * k + 1];
            {
                int tp = t + KC;
                float2 pq = (pv && tp <= Tc - 1) ? *(const float2*)(pc + (size_t)tp * SP)
                                                 : make_float2(0.f, 0.f);
                q[2 * k] = pq.x; q[2 * k + 1] = pq.y;
            }
            float fo = __shfl_up_sync(0xffffffffu, Ao, 1);   // A_{2i-1}
            float ne = (Ae + fo) * pe;
            float no = (Ao + Ae + skf * fo) * po;
            if (t < hlen) { Ae = ne; Ao = no; }

            if (k == 7) {   // barrier-free warp renorm
                float wm = fmaxf(Ae, Ao);
#pragma unroll
                for (int o = 16; o; o >>= 1)
                    wm = fmaxf(wm, __shfl_xor_sync(0xffffffffu, wm, o));
                wm = fmaxf(wm, 1e-30f);
                float r = __frcp_rn(wm);
                Ae *= r; Ao *= r;
                lc += __logf(wm);
            }
        }

        const float corr = m + lc - (float)n_sc * LOGV;
        ae = corr + __logf(fmaxf(Ae, 1e-37f));
        ao = corr + __logf(fmaxf(Ao, 1e-37f));
        nb ^= 1;
        if (own) {
            sbuf[nb][2 * i] = ae;
            if (ov) sbuf[nb][2 * i + 1] = ao;
            else if (i == 128) sbuf[nb][257] = NEGF;
        }
        __syncthreads();
    }

    if (tid == 0) {
        int   yl  = ylens[b];
        float abk = sbuf[nb][2 * yl];
        float alb = sbuf[nb][2 * yl - 1];
        float mm  = fmaxf(abk, alb);
        float aend = mm + __logf(__expf(abk - mm) + __expf(alb - mm));
        g_loss[b] = -aend / (float)yl;
    }
}

// ---------------------------------------------------------------------------
// Kernel 3: mean over batch -> scalar output.
// ---------------------------------------------------------------------------
__global__ void k_reduce(float* __restrict__ out)
{
    float v = g_loss[threadIdx.x];
#pragma unroll
    for (int o = 16; o; o >>= 1) v += __shfl_xor_sync(0xffffffffu, v, o);
    if (threadIdx.x == 0) out[0] = v / (float)Bc;
}

// ---------------------------------------------------------------------------
extern "C" void kernel_launch(void* const* d_in, const int* in_sizes, int n_in,
                              void* d_out, int out_size)
{
    const float* hs    = (const float*)d_in[0];   // (B,T,V) fp32
    const int*   hlens = (const int*)  d_in[1];   // (B,)
    const int*   ys    = (const int*)  d_in[2];   // (B,L)
    const int*   ylens = (const int*)  d_in[3];   // (B,)
    float* out = (float*)d_out;

    (void)in_sizes; (void)n_in; (void)out_size;

    k_prob<<<Bc * Tc / 8, 256>>>(hs, ys);
    k_ctc_dp<<<Bc, 288>>>(ys, hlens, ylens);
    k_reduce<<<1, 32>>>(out);
}